// round 5
// baseline (speedup 1.0000x reference)
#include <cuda_runtime.h>

namespace {

constexpr int Wn    = 64;     // timesteps
constexpr int En    = 16;     // ensembles
constexpr int BIn   = 2560;   // B*I
constexpr int Fn    = 8;      // input features
constexpr int PROJn = 16;     // projection dim
constexpr int NSEQ  = En * BIn;      // 40960 independent sequences
constexpr int TPB   = 128;           // grid = 320 CTAs
constexpr int CHUNK = 2;             // timesteps per pipeline stage
constexpr int NSTAGE = 4;            // stages; steady-state depth = 3 chunks
constexpr int NCHUNK = Wn / CHUNK;   // 32

__device__ __forceinline__ float fast_sigmoid(float x) {
    float t = __expf(-x);                 // MUFU.EX2 path
    return __fdividef(1.0f, 1.0f + t);   // MUFU.RCP path
}

__device__ __forceinline__ float fast_tanh(float x) {
    float t = __expf(-2.0f * x);
    return __fdividef(2.0f, 1.0f + t) - 1.0f;
}

__device__ __forceinline__ void cp_async16(void* smem_dst, const void* gmem_src) {
    unsigned s = (unsigned)__cvta_generic_to_shared(smem_dst);
    asm volatile("cp.async.cg.shared.global [%0], [%1], 16;"
                 :: "r"(s), "l"(gmem_src) : "memory");
}
__device__ __forceinline__ void cp_commit() {
    asm volatile("cp.async.commit_group;" ::: "memory");
}
__device__ __forceinline__ void cp_wait3() {
    asm volatile("cp.async.wait_group 3;" ::: "memory");
}

__global__ void __launch_bounds__(TPB) gru_fused_kernel(
    const float* __restrict__ x,      // (W, E, BI, F)
    const float* __restrict__ state,  // (1, E, BI, 1) -> NSEQ
    const float* __restrict__ wl,     // (E, PROJ, F)
    const float* __restrict__ bl,     // (E, PROJ)
    const float* __restrict__ wih,    // (E, 3, PROJ)
    const float* __restrict__ whh,    // (E, 3, 1)
    const float* __restrict__ bih,    // (E, 3)
    const float* __restrict__ bhh,    // (E, 3)
    float* __restrict__ out)          // (W, E, BI, 1)
{
    // smem staging: [stage][step][half][tid], 16B per lane -> conflict-free
    __shared__ float4 stg[NSTAGE * CHUNK * 2 * TPB];   // 32 KB

    const int tid = threadIdx.x;
    const int t = blockIdx.x * TPB + tid;   // sequence id, exact grid
    const int e = t / BIn;

    // ---- Fold the two input matmuls into one (3 x 8) matrix per ensemble ----
    float C[3][8];
    float cb[3];
    #pragma unroll
    for (int g = 0; g < 3; ++g) {
        cb[g] = bih[e * 3 + g];
        #pragma unroll
        for (int f = 0; f < 8; ++f) C[g][f] = 0.0f;
    }
    const float4* wlv = reinterpret_cast<const float4*>(wl + (size_t)e * PROJn * Fn);
    #pragma unroll
    for (int p = 0; p < PROJn; ++p) {
        float4 wa = wlv[p * 2 + 0];
        float4 wb = wlv[p * 2 + 1];
        float blp = bl[e * PROJn + p];
        #pragma unroll
        for (int g = 0; g < 3; ++g) {
            float wg = wih[(e * 3 + g) * PROJn + p];
            cb[g] = fmaf(wg, blp, cb[g]);
            C[g][0] = fmaf(wg, wa.x, C[g][0]);
            C[g][1] = fmaf(wg, wa.y, C[g][1]);
            C[g][2] = fmaf(wg, wa.z, C[g][2]);
            C[g][3] = fmaf(wg, wa.w, C[g][3]);
            C[g][4] = fmaf(wg, wb.x, C[g][4]);
            C[g][5] = fmaf(wg, wb.y, C[g][5]);
            C[g][6] = fmaf(wg, wb.z, C[g][6]);
            C[g][7] = fmaf(wg, wb.w, C[g][7]);
        }
    }
    const float whh0 = whh[e * 3 + 0], whh1 = whh[e * 3 + 1], whh2 = whh[e * 3 + 2];
    const float bhh0 = bhh[e * 3 + 0], bhh1 = bhh[e * 3 + 1], bhh2 = bhh[e * 3 + 2];

    float h = state[t];

    const float4* xv = reinterpret_cast<const float4*>(x) + (size_t)t * 2;
    float* outp = out + t;

    // Issue one chunk's loads into a stage (per-thread private slots).
    auto load_stage = [&](int st, int c) {
        #pragma unroll
        for (int s = 0; s < CHUNK; ++s) {
            const float4* src = xv + (size_t)(c * CHUNK + s) * (NSEQ * 2);
            cp_async16(&stg[((st * CHUNK + s) * 2 + 0) * TPB + tid], src);
            cp_async16(&stg[((st * CHUNK + s) * 2 + 1) * TPB + tid], src + 1);
        }
    };

    auto gru_step = [&](int w, float4 a, float4 b) {
        float gi0 = cb[0], gi1 = cb[1], gi2 = cb[2];
        gi0 = fmaf(C[0][0], a.x, gi0); gi1 = fmaf(C[1][0], a.x, gi1); gi2 = fmaf(C[2][0], a.x, gi2);
        gi0 = fmaf(C[0][1], a.y, gi0); gi1 = fmaf(C[1][1], a.y, gi1); gi2 = fmaf(C[2][1], a.y, gi2);
        gi0 = fmaf(C[0][2], a.z, gi0); gi1 = fmaf(C[1][2], a.z, gi1); gi2 = fmaf(C[2][2], a.z, gi2);
        gi0 = fmaf(C[0][3], a.w, gi0); gi1 = fmaf(C[1][3], a.w, gi1); gi2 = fmaf(C[2][3], a.w, gi2);
        gi0 = fmaf(C[0][4], b.x, gi0); gi1 = fmaf(C[1][4], b.x, gi1); gi2 = fmaf(C[2][4], b.x, gi2);
        gi0 = fmaf(C[0][5], b.y, gi0); gi1 = fmaf(C[1][5], b.y, gi1); gi2 = fmaf(C[2][5], b.y, gi2);
        gi0 = fmaf(C[0][6], b.z, gi0); gi1 = fmaf(C[1][6], b.z, gi1); gi2 = fmaf(C[2][6], b.z, gi2);
        gi0 = fmaf(C[0][7], b.w, gi0); gi1 = fmaf(C[1][7], b.w, gi1); gi2 = fmaf(C[2][7], b.w, gi2);

        float gh0 = fmaf(whh0, h, bhh0);
        float gh1 = fmaf(whh1, h, bhh1);
        float gh2 = fmaf(whh2, h, bhh2);

        float r = fast_sigmoid(gi0 + gh0);
        float z = fast_sigmoid(gi1 + gh1);
        float n = fast_tanh(fmaf(r, gh2, gi2));
        h = fmaf(z, h - n, n);                 // (1-z)*n + z*h
        __stcs(outp + (size_t)w * NSEQ, h);    // streaming store, no reuse
    };

    // Prime the pipeline: chunks 0..NSTAGE-2 in flight (3 groups).
    #pragma unroll
    for (int st = 0; st < NSTAGE - 1; ++st) {
        load_stage(st, st);
        cp_commit();
    }

    #pragma unroll 4   // = NSTAGE, so stage indices are compile-time static
    for (int c = 0; c < NCHUNK; ++c) {
        const int st = c & (NSTAGE - 1);
        const int cp = c + NSTAGE - 1;
        if (cp < NCHUNK) load_stage(cp & (NSTAGE - 1), cp);
        cp_commit();            // commit every iter (possibly empty) for stable accounting
        cp_wait3();             // chunk c's group is now complete

        #pragma unroll
        for (int s = 0; s < CHUNK; ++s) {
            float4 a = stg[((st * CHUNK + s) * 2 + 0) * TPB + tid];
            float4 b = stg[((st * CHUNK + s) * 2 + 1) * TPB + tid];
            gru_step(c * CHUNK + s, a, b);
        }
    }
}

}  // namespace

extern "C" void kernel_launch(void* const* d_in, const int* in_sizes, int n_in,
                              void* d_out, int out_size) {
    (void)in_sizes; (void)n_in; (void)out_size;
    const float* x     = (const float*)d_in[0];
    const float* state = (const float*)d_in[1];
    const float* wl    = (const float*)d_in[2];
    const float* bl    = (const float*)d_in[3];
    const float* wih   = (const float*)d_in[4];
    const float* whh   = (const float*)d_in[5];
    const float* bih   = (const float*)d_in[6];
    const float* bhh   = (const float*)d_in[7];
    float* out = (float*)d_out;

    const int blocks = NSEQ / TPB;  // 40960 / 128 = 320, exact
    gru_fused_kernel<<<blocks, TPB>>>(x, state, wl, bl, wih, whh, bih, bhh, out);
}

// round 6
// speedup vs baseline: 1.5663x; 1.5663x over previous
#include <cuda_runtime.h>

namespace {

constexpr int Wn    = 64;     // timesteps
constexpr int En    = 16;     // ensembles
constexpr int BIn   = 2560;   // B*I
constexpr int PROJn = 16;     // projection dim
constexpr int NSEQ  = En * BIn;      // 40960 independent sequences
constexpr int NTHR  = NSEQ * 2;      // 2 threads per sequence
constexpr int CHUNK = 4;             // timesteps per register chunk
constexpr int NCHUNK = Wn / CHUNK;   // 16
constexpr int TPB   = 128;           // 640 CTAs

__device__ __forceinline__ float fast_sigmoid(float x) {
    float t = __expf(-x);                 // MUFU.EX2 path
    return __fdividef(1.0f, 1.0f + t);   // MUFU.RCP path
}

__device__ __forceinline__ float fast_tanh(float x) {
    float t = __expf(-2.0f * x);
    return __fdividef(2.0f, 1.0f + t) - 1.0f;
}

__global__ void __launch_bounds__(TPB) gru_fused_kernel(
    const float* __restrict__ x,      // (W, E, BI, F=8)
    const float* __restrict__ state,  // (1, E, BI, 1) -> NSEQ
    const float* __restrict__ wl,     // (E, PROJ, F)
    const float* __restrict__ bl,     // (E, PROJ)
    const float* __restrict__ wih,    // (E, 3, PROJ)
    const float* __restrict__ whh,    // (E, 3, 1)
    const float* __restrict__ bih,    // (E, 3)
    const float* __restrict__ bhh,    // (E, 3)
    float* __restrict__ out)          // (W, E, BI, 1)
{
    const int g    = blockIdx.x * TPB + threadIdx.x;  // 0..NTHR-1
    const int seq  = g >> 1;                          // sequence id
    const int half = g & 1;                           // which 4 features
    const int e    = seq / BIn;

    // ---- Fold the two input matmuls; this lane keeps only its 4 features ----
    // C[g][f'] = sum_p wih[e,g,p] * wl[e,p,half*4+f'] ; cb = bih + wih.bl (full)
    float C[3][4];
    float cb[3];
    #pragma unroll
    for (int gg = 0; gg < 3; ++gg) {
        cb[gg] = bih[e * 3 + gg];
        #pragma unroll
        for (int f = 0; f < 4; ++f) C[gg][f] = 0.0f;
    }
    const float4* wlv = reinterpret_cast<const float4*>(wl + (size_t)e * PROJn * 8);
    #pragma unroll
    for (int p = 0; p < PROJn; ++p) {
        float4 wv = wlv[p * 2 + half];            // this lane's 4 features of row p
        float blp = bl[e * PROJn + p];
        #pragma unroll
        for (int gg = 0; gg < 3; ++gg) {
            float wg = wih[(e * 3 + gg) * PROJn + p];
            cb[gg] = fmaf(wg, blp, cb[gg]);
            C[gg][0] = fmaf(wg, wv.x, C[gg][0]);
            C[gg][1] = fmaf(wg, wv.y, C[gg][1]);
            C[gg][2] = fmaf(wg, wv.z, C[gg][2]);
            C[gg][3] = fmaf(wg, wv.w, C[gg][3]);
        }
    }
    const float whh0 = whh[e * 3 + 0], whh1 = whh[e * 3 + 1], whh2 = whh[e * 3 + 2];
    const float bhh0 = bhh[e * 3 + 0], bhh1 = bhh[e * 3 + 1], bhh2 = bhh[e * 3 + 2];

    float h = state[seq];

    // Lane's float4 slot for timestep w: x viewed as float4[(w*NSEQ + seq)*2 + half]
    const float4* xv = reinterpret_cast<const float4*>(x) + (size_t)seq * 2 + half;
    float* outp = out + seq;

    float4 bufA[CHUNK];
    float4 bufB[CHUNK];

    auto gru_step = [&](int w, float4 a) {
        // partial gi over this lane's 4 features
        float p0 = C[0][0] * a.x, p1 = C[1][0] * a.x, p2 = C[2][0] * a.x;
        p0 = fmaf(C[0][1], a.y, p0); p1 = fmaf(C[1][1], a.y, p1); p2 = fmaf(C[2][1], a.y, p2);
        p0 = fmaf(C[0][2], a.z, p0); p1 = fmaf(C[1][2], a.z, p1); p2 = fmaf(C[2][2], a.z, p2);
        p0 = fmaf(C[0][3], a.w, p0); p1 = fmaf(C[1][3], a.w, p1); p2 = fmaf(C[2][3], a.w, p2);
        // combine halves across the lane pair
        float gi0 = p0 + __shfl_xor_sync(0xffffffffu, p0, 1) + cb[0];
        float gi1 = p1 + __shfl_xor_sync(0xffffffffu, p1, 1) + cb[1];
        float gi2 = p2 + __shfl_xor_sync(0xffffffffu, p2, 1) + cb[2];

        float gh0 = fmaf(whh0, h, bhh0);
        float gh1 = fmaf(whh1, h, bhh1);
        float gh2 = fmaf(whh2, h, bhh2);

        float r = fast_sigmoid(gi0 + gh0);
        float z = fast_sigmoid(gi1 + gh1);
        float n = fast_tanh(fmaf(r, gh2, gi2));
        h = fmaf(z, h - n, n);                 // (1-z)*n + z*h
        if (half == 0)
            __stcs(outp + (size_t)w * NSEQ, h);
    };

    auto load_chunk = [&](float4 (&dst)[CHUNK], int c) {
        #pragma unroll
        for (int s = 0; s < CHUNK; ++s)
            dst[s] = __ldcs(xv + (size_t)(c * CHUNK + s) * (NSEQ * 2));
    };

    auto do_chunk = [&](float4 (&cur)[CHUNK], float4 (&nxt)[CHUNK], int c) {
        if (c + 1 < NCHUNK) load_chunk(nxt, c + 1);   // prefetch next chunk
        #pragma unroll
        for (int s = 0; s < CHUNK; ++s)
            gru_step(c * CHUNK + s, cur[s]);
    };

    load_chunk(bufA, 0);

    #pragma unroll
    for (int c = 0; c < NCHUNK; ++c) {
        if (c & 1) do_chunk(bufB, bufA, c);
        else       do_chunk(bufA, bufB, c);
    }
}

}  // namespace

extern "C" void kernel_launch(void* const* d_in, const int* in_sizes, int n_in,
                              void* d_out, int out_size) {
    (void)in_sizes; (void)n_in; (void)out_size;
    const float* x     = (const float*)d_in[0];
    const float* state = (const float*)d_in[1];
    const float* wl    = (const float*)d_in[2];
    const float* bl    = (const float*)d_in[3];
    const float* wih   = (const float*)d_in[4];
    const float* whh   = (const float*)d_in[5];
    const float* bih   = (const float*)d_in[6];
    const float* bhh   = (const float*)d_in[7];
    float* out = (float*)d_out;

    const int blocks = NTHR / TPB;  // 81920 / 128 = 640, exact
    gru_fused_kernel<<<blocks, TPB>>>(x, state, wl, bl, wih, whh, bih, bhh, out);
}